// round 1
// baseline (speedup 1.0000x reference)
#include <cuda_runtime.h>
#include <cuda_bf16.h>
#include <cstdint>

// ---------------- problem constants ----------------
#define N_NODES 100000
#define N_EDGES 1600000
#define IN_DIM 64
#define HID 128
#define OUT_DIM 9

// ---------------- scratch (static device memory; no allocation allowed) ----
__device__ float g_deg[N_NODES];
__device__ float g_agg[(size_t)N_NODES * HID];        // max agg feature dim = 128
__device__ float g_h1[(size_t)N_NODES * HID];
__device__ float g_h2[(size_t)N_NODES * HID];
__device__ float g_h3[(size_t)N_NODES * 2 * HID];

// ---------------- small utility kernels ----------------
__global__ void zero_kernel(float* __restrict__ p, int n) {
    int i = blockIdx.x * blockDim.x + threadIdx.x;
    if (i < n) p[i] = 0.0f;
}

__global__ void deg_kernel(const int* __restrict__ dst, float* __restrict__ deg, int E) {
    int e = blockIdx.x * blockDim.x + threadIdx.x;
    if (e < E) atomicAdd(&deg[dst[e]], 1.0f);
}

// scatter-add: agg[dst[e]][:] += x[src[e]][:]   (vectorized float4, red.global)
// dv = d/4 (float4 units), shift = log2(dv)
__global__ void scatter_kernel(const float4* __restrict__ x,
                               const int* __restrict__ src,
                               const int* __restrict__ dst,
                               float4* __restrict__ agg,
                               int E, int shift) {
    int idx = blockIdx.x * blockDim.x + threadIdx.x;
    int dv = 1 << shift;
    if (idx >= E * dv) return;
    int e = idx >> shift;
    int c = idx & (dv - 1);
    int s = src[e];
    int d = dst[e];
    float4 v = x[((size_t)s << shift) + c];
    float4* p = &agg[((size_t)d << shift) + c];
    asm volatile("red.global.add.v4.f32 [%0], {%1, %2, %3, %4};"
                 :: "l"(p), "f"(v.x), "f"(v.y), "f"(v.z), "f"(v.w)
                 : "memory");
}

// agg[i][:] *= 1/max(deg[i],1)
__global__ void mean_kernel(float4* __restrict__ agg, const float* __restrict__ deg,
                            int n_nodes, int shift) {
    int idx = blockIdx.x * blockDim.x + threadIdx.x;
    int dv = 1 << shift;
    if (idx >= n_nodes * dv) return;
    int i = idx >> shift;
    float r = 1.0f / fmaxf(deg[i], 1.0f);
    float4 v = agg[idx];
    v.x *= r; v.y *= r; v.z *= r; v.w *= r;
    agg[idx] = v;
}

// ---------------- dual-A SGEMM: C = relu(A1@W1 + A2@W2 + bias) ----------------
// BM=128, BN=128, BK=8, 256 threads, 8x8 per thread.
// A1: [M,K1] row-major, A2: [M,K2] row-major, W*: [K*, N] row-major.
template <bool RELU>
__global__ __launch_bounds__(256)
void gemm_dual(const float* __restrict__ A1, int K1, const float* __restrict__ W1,
               const float* __restrict__ A2, int K2, const float* __restrict__ W2,
               const float* __restrict__ bias, float* __restrict__ C,
               int M, int N) {
    constexpr int BM = 128, BN = 128, BK = 8;
    __shared__ float As[BK][BM + 4];   // +4 pad: conflict-free store pattern
    __shared__ float Bs[BK][BN];

    const int bm = blockIdx.x * BM;
    const int bn = blockIdx.y * BN;
    const int tid = threadIdx.x;

    const int a_row = tid >> 1;              // 0..127
    const int a_col = (tid & 1) << 2;        // 0 or 4
    const int b_row = tid >> 5;              // 0..7
    const int b_col = (tid & 31) << 2;       // 0..124

    const int ty = tid >> 4;                 // 0..15
    const int tx = tid & 15;                 // 0..15

    float acc[8][8];
    #pragma unroll
    for (int m = 0; m < 8; m++)
        #pragma unroll
        for (int n = 0; n < 8; n++) acc[m][n] = 0.0f;

    const int K = K1 + K2;
    for (int kt = 0; kt < K; kt += BK) {
        const float* A; const float* W; int lda; int koff;
        if (kt < K1) { A = A1; W = W1; lda = K1; koff = kt; }
        else         { A = A2; W = W2; lda = K2; koff = kt - K1; }

        // load A tile (128 x 8), transposed into As
        int grow = bm + a_row;
        float4 av = make_float4(0.f, 0.f, 0.f, 0.f);
        if (grow < M)
            av = *reinterpret_cast<const float4*>(A + (size_t)grow * lda + koff + a_col);
        As[a_col + 0][a_row] = av.x;
        As[a_col + 1][a_row] = av.y;
        As[a_col + 2][a_row] = av.z;
        As[a_col + 3][a_row] = av.w;

        // load B tile (8 x 128) — weight rows always valid, cols valid (N % 128 == 0)
        float4 bv = *reinterpret_cast<const float4*>(W + (size_t)(koff + b_row) * N + bn + b_col);
        *reinterpret_cast<float4*>(&Bs[b_row][b_col]) = bv;

        __syncthreads();

        #pragma unroll
        for (int k = 0; k < BK; k++) {
            float4 ra0 = *reinterpret_cast<const float4*>(&As[k][ty * 8]);
            float4 ra1 = *reinterpret_cast<const float4*>(&As[k][ty * 8 + 4]);
            float4 rb0 = *reinterpret_cast<const float4*>(&Bs[k][tx * 8]);
            float4 rb1 = *reinterpret_cast<const float4*>(&Bs[k][tx * 8 + 4]);
            float ra[8] = {ra0.x, ra0.y, ra0.z, ra0.w, ra1.x, ra1.y, ra1.z, ra1.w};
            float rb[8] = {rb0.x, rb0.y, rb0.z, rb0.w, rb1.x, rb1.y, rb1.z, rb1.w};
            #pragma unroll
            for (int m = 0; m < 8; m++)
                #pragma unroll
                for (int n = 0; n < 8; n++)
                    acc[m][n] = fmaf(ra[m], rb[n], acc[m][n]);
        }
        __syncthreads();
    }

    #pragma unroll
    for (int m = 0; m < 8; m++) {
        int row = bm + ty * 8 + m;
        if (row >= M) continue;
        #pragma unroll
        for (int n = 0; n < 8; n++) {
            int col = bn + tx * 8 + n;
            float v = acc[m][n] + bias[col];
            if (RELU) v = fmaxf(v, 0.0f);
            C[(size_t)row * N + col] = v;
        }
    }
}

// ---------------- FC head: out[i,0..8] = h3[i,:]@Wfc + bfc (warp per node) ----
__global__ void fc_kernel(const float* __restrict__ h3, const float* __restrict__ W,
                          const float* __restrict__ b, float* __restrict__ out, int M) {
    int gwarp = (blockIdx.x * blockDim.x + threadIdx.x) >> 5;
    int lane = threadIdx.x & 31;
    if (gwarp >= M) return;
    const float* row = h3 + (size_t)gwarp * (2 * HID);
    float acc[OUT_DIM];
    #pragma unroll
    for (int j = 0; j < OUT_DIM; j++) acc[j] = 0.0f;
    for (int k = lane; k < 2 * HID; k += 32) {
        float a = row[k];
        #pragma unroll
        for (int j = 0; j < OUT_DIM; j++)
            acc[j] = fmaf(a, W[k * OUT_DIM + j], acc[j]);
    }
    #pragma unroll
    for (int j = 0; j < OUT_DIM; j++) {
        #pragma unroll
        for (int off = 16; off > 0; off >>= 1)
            acc[j] += __shfl_down_sync(0xffffffffu, acc[j], off);
    }
    if (lane == 0) {
        #pragma unroll
        for (int j = 0; j < OUT_DIM; j++)
            out[(size_t)gwarp * OUT_DIM + j] = acc[j] + b[j];
    }
}

// ---------------- host launch ----------------
static inline int cdiv(int a, int b) { return (a + b - 1) / b; }

extern "C" void kernel_launch(void* const* d_in, const int* in_sizes, int n_in,
                              void* d_out, int out_size) {
    const float* x   = (const float*)d_in[0];
    const int* eidx  = (const int*)d_in[1];
    const float* Wl1 = (const float*)d_in[2];
    const float* bl1 = (const float*)d_in[3];
    const float* Wr1 = (const float*)d_in[4];
    const float* Wl2 = (const float*)d_in[5];
    const float* bl2 = (const float*)d_in[6];
    const float* Wr2 = (const float*)d_in[7];
    const float* Wl3 = (const float*)d_in[8];
    const float* bl3 = (const float*)d_in[9];
    const float* Wr3 = (const float*)d_in[10];
    const float* Wfc = (const float*)d_in[11];
    const float* bfc = (const float*)d_in[12];
    float* out = (float*)d_out;

    const int M = in_sizes[0] / IN_DIM;       // 100000
    const int E = in_sizes[1] / 2;            // 1600000
    const int* src = eidx;
    const int* dst = eidx + E;

    float *deg, *agg, *h1, *h2, *h3;
    cudaGetSymbolAddress((void**)&deg, g_deg);
    cudaGetSymbolAddress((void**)&agg, g_agg);
    cudaGetSymbolAddress((void**)&h1, g_h1);
    cudaGetSymbolAddress((void**)&h2, g_h2);
    cudaGetSymbolAddress((void**)&h3, g_h3);

    const int T = 256;

    // degree (reused by all 3 layers)
    zero_kernel<<<cdiv(M, T), T>>>(deg, M);
    deg_kernel<<<cdiv(E, T), T>>>(dst, deg, E);

    dim3 g1(cdiv(M, 128), 1);
    dim3 g2(cdiv(M, 128), 2);

    // ---- layer 1: d = 64 ----
    {
        const int d = IN_DIM, shift = 4;                  // dv = 16
        zero_kernel<<<cdiv(M * d, T), T>>>(agg, M * d);
        scatter_kernel<<<cdiv(E * (d / 4), T), T>>>(
            (const float4*)x, src, dst, (float4*)agg, E, shift);
        mean_kernel<<<cdiv(M * (d / 4), T), T>>>((float4*)agg, deg, M, shift);
        gemm_dual<true><<<g1, 256>>>(agg, d, Wl1, x, d, Wr1, bl1, h1, M, HID);
    }
    // ---- layer 2: d = 128 ----
    {
        const int d = HID, shift = 5;                     // dv = 32
        zero_kernel<<<cdiv(M * d, T), T>>>(agg, M * d);
        scatter_kernel<<<cdiv(E * (d / 4), T), T>>>(
            (const float4*)h1, src, dst, (float4*)agg, E, shift);
        mean_kernel<<<cdiv(M * (d / 4), T), T>>>((float4*)agg, deg, M, shift);
        gemm_dual<true><<<g1, 256>>>(agg, d, Wl2, h1, d, Wr2, bl2, h2, M, HID);
    }
    // ---- layer 3: d = 128 -> 256 ----
    {
        const int d = HID, shift = 5;
        zero_kernel<<<cdiv(M * d, T), T>>>(agg, M * d);
        scatter_kernel<<<cdiv(E * (d / 4), T), T>>>(
            (const float4*)h2, src, dst, (float4*)agg, E, shift);
        mean_kernel<<<cdiv(M * (d / 4), T), T>>>((float4*)agg, deg, M, shift);
        gemm_dual<true><<<g2, 256>>>(agg, d, Wl3, h2, d, Wr3, bl3, h3, M, 2 * HID);
    }
    // ---- FC head ----
    fc_kernel<<<cdiv(M * 32, T), T>>>(h3, Wfc, bfc, out, M);
}

// round 5
// speedup vs baseline: 1.3170x; 1.3170x over previous
#include <cuda_runtime.h>
#include <cuda_bf16.h>
#include <cstdint>

// ---------------- problem constants ----------------
#define N_NODES 100000
#define N_EDGES 1600000
#define IN_DIM 64
#define HID 128
#define OUT_DIM 9

// ---------------- static scratch (no allocation allowed) ----------------
__device__ float g_deg[N_NODES];
__device__ float g_agg[(size_t)N_NODES * HID];                 // fp32 scatter accumulator
__device__ __nv_bfloat16 g_xhi[(size_t)N_NODES * IN_DIM];
__device__ __nv_bfloat16 g_xlo[(size_t)N_NODES * IN_DIM];
__device__ __nv_bfloat16 g_mhi[(size_t)N_NODES * HID];         // mean hi
__device__ __nv_bfloat16 g_mlo[(size_t)N_NODES * HID];         // mean lo
__device__ float g_h[(size_t)N_NODES * HID];                   // h1 then h2 (fp32, for scatter)
__device__ __nv_bfloat16 g_hhi[(size_t)N_NODES * HID];
__device__ __nv_bfloat16 g_hlo[(size_t)N_NODES * HID];
__device__ float g_h3[(size_t)N_NODES * 2 * HID];
// static weight buffers (bf16, transposed [N,K]); order: l1l_hi,l1l_lo,l1r_hi,l1r_lo, l2..., l3...
__device__ __nv_bfloat16 g_w[12][256 * 128];

// ---------------- PTX helpers (all plain sm_80+ — no 'a' features) ----------------
__device__ __forceinline__ uint32_t smem_u32(const void* p) {
    uint32_t a;
    asm("{ .reg .u64 t; cvta.to.shared.u64 t, %1; cvt.u32.u64 %0, t; }" : "=r"(a) : "l"(p));
    return a;
}

__device__ __forceinline__ void cp_async16(uint32_t dst, const void* src, int src_bytes) {
    asm volatile("cp.async.cg.shared.global [%0], [%1], 16, %2;"
                 :: "r"(dst), "l"(src), "r"(src_bytes));
}
#define CP_COMMIT() asm volatile("cp.async.commit_group;" ::: "memory")
#define CP_WAIT_1() asm volatile("cp.async.wait_group 1;" ::: "memory")

__device__ __forceinline__ void ldm_x4(uint32_t& r0, uint32_t& r1, uint32_t& r2, uint32_t& r3,
                                       uint32_t addr) {
    asm volatile("ldmatrix.sync.aligned.m8n8.x4.shared.b16 {%0,%1,%2,%3}, [%4];"
                 : "=r"(r0), "=r"(r1), "=r"(r2), "=r"(r3) : "r"(addr));
}

__device__ __forceinline__ void mma_16816(float* c, const uint32_t* a, const uint32_t* b) {
    asm volatile(
        "mma.sync.aligned.m16n8k16.row.col.f32.bf16.bf16.f32 "
        "{%0,%1,%2,%3}, {%4,%5,%6,%7}, {%8,%9}, {%0,%1,%2,%3};"
        : "+f"(c[0]), "+f"(c[1]), "+f"(c[2]), "+f"(c[3])
        : "r"(a[0]), "r"(a[1]), "r"(a[2]), "r"(a[3]), "r"(b[0]), "r"(b[1]));
}

// ---------------- utility kernels ----------------
__global__ void zero_kernel(float* __restrict__ p, int n) {
    int i = blockIdx.x * blockDim.x + threadIdx.x;
    if (i < n) p[i] = 0.0f;
}

__global__ void deg_kernel(const int* __restrict__ dst, float* __restrict__ deg, int E) {
    int e = blockIdx.x * blockDim.x + threadIdx.x;
    if (e < E) atomicAdd(&deg[dst[e]], 1.0f);
}

// scatter-add: agg[dst[e]][:] += x[src[e]][:]   (vectorized float4, red.global)
__global__ void scatter_kernel(const float4* __restrict__ x,
                               const int* __restrict__ src,
                               const int* __restrict__ dst,
                               float4* __restrict__ agg,
                               int E, int shift) {
    int idx = blockIdx.x * blockDim.x + threadIdx.x;
    int dv = 1 << shift;
    if (idx >= E * dv) return;
    int e = idx >> shift;
    int c = idx & (dv - 1);
    int s = src[e];
    int d = dst[e];
    float4 v = x[((size_t)s << shift) + c];
    float4* p = &agg[((size_t)d << shift) + c];
    asm volatile("red.global.add.v4.f32 [%0], {%1, %2, %3, %4};"
                 :: "l"(p), "f"(v.x), "f"(v.y), "f"(v.z), "f"(v.w)
                 : "memory");
}

// mean + bf16 hi/lo split
__global__ void mean_conv_kernel(const float* __restrict__ agg, const float* __restrict__ deg,
                                 __nv_bfloat16* __restrict__ hi, __nv_bfloat16* __restrict__ lo,
                                 int total, int dshift) {
    int idx = blockIdx.x * blockDim.x + threadIdx.x;
    if (idx >= total) return;
    int i = idx >> dshift;
    float r = 1.0f / fmaxf(deg[i], 1.0f);
    float m = agg[idx] * r;
    __nv_bfloat16 h = __float2bfloat16(m);
    hi[idx] = h;
    lo[idx] = __float2bfloat16(m - __bfloat162float(h));
}

// fp32 -> bf16 hi/lo elementwise (for x)
__global__ void split_kernel(const float* __restrict__ x,
                             __nv_bfloat16* __restrict__ hi, __nv_bfloat16* __restrict__ lo, int n) {
    int i = blockIdx.x * blockDim.x + threadIdx.x;
    if (i >= n) return;
    float v = x[i];
    __nv_bfloat16 h = __float2bfloat16(v);
    hi[i] = h;
    lo[i] = __float2bfloat16(v - __bfloat162float(h));
}

// weight [K,N] fp32 -> transposed [N,K] bf16 hi/lo
__global__ void wsplit_kernel(const float* __restrict__ W,
                              __nv_bfloat16* __restrict__ hi, __nv_bfloat16* __restrict__ lo,
                              int K, int N) {
    int idx = blockIdx.x * blockDim.x + threadIdx.x;
    if (idx >= K * N) return;
    int k = idx / N, n = idx % N;
    float v = W[idx];
    __nv_bfloat16 h = __float2bfloat16(v);
    hi[(size_t)n * K + k] = h;
    lo[(size_t)n * K + k] = __float2bfloat16(v - __bfloat162float(h));
}

// ---------------- mma.sync dual-A split-bf16 GEMM ----------------
// C[128-tile x 128-tile] = relu( A1@B1^T + A2@B2^T + bias ), 3-term bf16 split:
//   segments (A1hi,B1hi)(A1hi,B1lo)(A1lo,B1hi)(A2hi,B2hi)(A2hi,B2lo)(A2lo,B2hi)
// A*: [M, Kseg] bf16 row-major.  B*: [Ntot, Kseg] bf16 row-major (= B^T, col-major B).
// CTA: 256 thr = 8 warps (4 M x 2 N), warp tile 32x64, BK = 64 (one chunk-stage).
// smem tile rows = 128 B (64 bf16), chunk(16B) swizzle: ch' = ch ^ (row & 7).
template <bool SPLIT_OUT>
__global__ __launch_bounds__(256, 2)
void gemm_mma(const __nv_bfloat16* __restrict__ A1hi, const __nv_bfloat16* __restrict__ A1lo,
              const __nv_bfloat16* __restrict__ A2hi, const __nv_bfloat16* __restrict__ A2lo,
              const __nv_bfloat16* __restrict__ B1hi, const __nv_bfloat16* __restrict__ B1lo,
              const __nv_bfloat16* __restrict__ B2hi, const __nv_bfloat16* __restrict__ B2lo,
              const float* __restrict__ bias, float* __restrict__ C,
              __nv_bfloat16* __restrict__ Chi, __nv_bfloat16* __restrict__ Clo,
              int M, int Ntot, int Kseg) {
    extern __shared__ char smem_raw[];
    // align tile base to 128 B for swizzle correctness
    char* smem = (char*)(((uintptr_t)smem_raw + 127) & ~(uintptr_t)127);
    const uint32_t sbase = smem_u32(smem);

    const int tid = threadIdx.x;
    const int wid = tid >> 5;
    const int lane = tid & 31;
    const int warp_m = wid & 3;          // 0..3 -> rows warp_m*32
    const int warp_n = wid >> 2;         // 0..1 -> cols warp_n*64
    const int bm = blockIdx.x * 128;
    const int bn = blockIdx.y * 128;

    // stage layout: [stage][A 16KB | B 16KB]
    const int STG = 32768;
    const int BOFF = 16384;

    const __nv_bfloat16* As[6] = {A1hi, A1hi, A1lo, A2hi, A2hi, A2lo};
    const __nv_bfloat16* Bs[6] = {B1hi, B1lo, B1hi, B2hi, B2lo, B2hi};
    const int cps = Kseg >> 6;           // chunk-stages per segment (1 or 2)
    const int nch = 6 * cps;

    // per-thread load coordinates (4 16B chunks for A, 4 for B per stage)
    // chunk index ci = tid + p*256 ; row = ci>>3 (0..127), ch = ci&7
    float acc[2][8][4];
    #pragma unroll
    for (int mi = 0; mi < 2; mi++)
        #pragma unroll
        for (int ni = 0; ni < 8; ni++)
            #pragma unroll
            for (int q = 0; q < 4; q++) acc[mi][ni][q] = 0.0f;

    auto load_stage = [&](int stage, int c) {
        const int seg = c / cps;
        const int sub = c - seg * cps;
        const __nv_bfloat16* Ab = As[seg];
        const __nv_bfloat16* Bb = Bs[seg];
        const int kofs = sub << 6;       // element offset within segment
        #pragma unroll
        for (int p = 0; p < 4; p++) {
            int ci = tid + p * 256;
            int row = ci >> 3;
            int ch = ci & 7;
            uint32_t dst = sbase + stage * STG + row * 128 + ((ch ^ (row & 7)) << 4);
            int grow = bm + row;
            int ok = (grow < M) ? 16 : 0;
            int gr = (grow < M) ? grow : (M - 1);
            cp_async16(dst, Ab + (size_t)gr * Kseg + kofs + ch * 8, ok);
        }
        #pragma unroll
        for (int p = 0; p < 4; p++) {
            int ci = tid + p * 256;
            int row = ci >> 3;
            int ch = ci & 7;
            uint32_t dst = sbase + stage * STG + BOFF + row * 128 + ((ch ^ (row & 7)) << 4);
            cp_async16(dst, Bb + (size_t)(bn + row) * Kseg + kofs + ch * 8, 16);
        }
    };

    // ldmatrix per-thread address components
    const int arow = warp_m * 32 + (lane & 15);          // + mi*16
    const int asel = (lane >> 4);                        // chunk offset 0/1 within k16
    const int brow = warp_n * 64 + (lane & 7) + ((lane & 16) >> 1);  // + nj*16
    const int bsel = (lane >> 3) & 1;

    load_stage(0, 0);
    CP_COMMIT();

    for (int c = 0; c < nch; c++) {
        const int s = c & 1;
        if (c + 1 < nch) load_stage(s ^ 1, c + 1);
        CP_COMMIT();
        CP_WAIT_1();
        __syncthreads();

        const uint32_t Abase = sbase + s * STG;
        const uint32_t Bbase = sbase + s * STG + BOFF;
        #pragma unroll
        for (int kc = 0; kc < 4; kc++) {
            uint32_t a[2][4];
            #pragma unroll
            for (int mi = 0; mi < 2; mi++) {
                int r = arow + mi * 16;
                uint32_t ad = Abase + r * 128 + (((kc * 2 + asel) ^ (r & 7)) << 4);
                ldm_x4(a[mi][0], a[mi][1], a[mi][2], a[mi][3], ad);
            }
            uint32_t b[8][2];
            #pragma unroll
            for (int nj = 0; nj < 4; nj++) {
                int r = brow + nj * 16;
                uint32_t bd = Bbase + r * 128 + (((kc * 2 + bsel) ^ (r & 7)) << 4);
                uint32_t t0, t1, t2, t3;
                ldm_x4(t0, t1, t2, t3, bd);
                b[nj * 2][0] = t0; b[nj * 2][1] = t1;
                b[nj * 2 + 1][0] = t2; b[nj * 2 + 1][1] = t3;
            }
            #pragma unroll
            for (int mi = 0; mi < 2; mi++)
                #pragma unroll
                for (int ni = 0; ni < 8; ni++)
                    mma_16816(acc[mi][ni], a[mi], b[ni]);
        }
        __syncthreads();
    }

    // ---------------- epilogue: bias + relu (+ hi/lo bf16 split) ----------------
    const int col0 = bn + warp_n * 64 + (lane & 3) * 2;
    #pragma unroll
    for (int mi = 0; mi < 2; mi++) {
        int row0 = bm + warp_m * 32 + mi * 16 + (lane >> 2);
        #pragma unroll
        for (int half = 0; half < 2; half++) {   // c0,c1 (row0) / c2,c3 (row0+8)
            int row = row0 + half * 8;
            if (row >= M) continue;
            #pragma unroll
            for (int ni = 0; ni < 8; ni++) {
                int col = col0 + ni * 8;
                float v0 = acc[mi][ni][half * 2 + 0] + __ldg(&bias[col]);
                float v1 = acc[mi][ni][half * 2 + 1] + __ldg(&bias[col + 1]);
                v0 = fmaxf(v0, 0.0f);
                v1 = fmaxf(v1, 0.0f);
                *(float2*)(C + (size_t)row * Ntot + col) = make_float2(v0, v1);
                if (SPLIT_OUT) {
                    __nv_bfloat16 h0 = __float2bfloat16(v0);
                    __nv_bfloat16 h1 = __float2bfloat16(v1);
                    __nv_bfloat16 l0 = __float2bfloat16(v0 - __bfloat162float(h0));
                    __nv_bfloat16 l1 = __float2bfloat16(v1 - __bfloat162float(h1));
                    *(__nv_bfloat162*)(Chi + (size_t)row * Ntot + col) = __nv_bfloat162(h0, h1);
                    *(__nv_bfloat162*)(Clo + (size_t)row * Ntot + col) = __nv_bfloat162(l0, l1);
                }
            }
        }
    }
}

// ---------------- FC head: out[i,0..8] = h3[i,:]@Wfc + bfc (warp per node) ----
__global__ void fc_kernel(const float* __restrict__ h3, const float* __restrict__ W,
                          const float* __restrict__ b, float* __restrict__ out, int M) {
    int gwarp = (blockIdx.x * blockDim.x + threadIdx.x) >> 5;
    int lane = threadIdx.x & 31;
    if (gwarp >= M) return;
    const float* row = h3 + (size_t)gwarp * (2 * HID);
    float acc[OUT_DIM];
    #pragma unroll
    for (int j = 0; j < OUT_DIM; j++) acc[j] = 0.0f;
    for (int k = lane; k < 2 * HID; k += 32) {
        float a = row[k];
        #pragma unroll
        for (int j = 0; j < OUT_DIM; j++)
            acc[j] = fmaf(a, W[k * OUT_DIM + j], acc[j]);
    }
    #pragma unroll
    for (int j = 0; j < OUT_DIM; j++) {
        #pragma unroll
        for (int off = 16; off > 0; off >>= 1)
            acc[j] += __shfl_down_sync(0xffffffffu, acc[j], off);
    }
    if (lane == 0) {
        #pragma unroll
        for (int j = 0; j < OUT_DIM; j++)
            out[(size_t)gwarp * OUT_DIM + j] = acc[j] + b[j];
    }
}

// ---------------- host launch ----------------
static inline int cdiv(int a, int b) { return (a + b - 1) / b; }

extern "C" void kernel_launch(void* const* d_in, const int* in_sizes, int n_in,
                              void* d_out, int out_size) {
    const float* x   = (const float*)d_in[0];
    const int* eidx  = (const int*)d_in[1];
    const float* Wl1 = (const float*)d_in[2];
    const float* bl1 = (const float*)d_in[3];
    const float* Wr1 = (const float*)d_in[4];
    const float* Wl2 = (const float*)d_in[5];
    const float* bl2 = (const float*)d_in[6];
    const float* Wr2 = (const float*)d_in[7];
    const float* Wl3 = (const float*)d_in[8];
    const float* bl3 = (const float*)d_in[9];
    const float* Wr3 = (const float*)d_in[10];
    const float* Wfc = (const float*)d_in[11];
    const float* bfc = (const float*)d_in[12];
    float* out = (float*)d_out;

    const int M = in_sizes[0] / IN_DIM;       // 100000
    const int E = in_sizes[1] / 2;            // 1600000
    const int* src = eidx;
    const int* dst = eidx + E;

    float *deg, *agg, *h, *h3;
    __nv_bfloat16 *xhi, *xlo, *mhi, *mlo, *hhi, *hlo, *w;
    cudaGetSymbolAddress((void**)&deg, g_deg);
    cudaGetSymbolAddress((void**)&agg, g_agg);
    cudaGetSymbolAddress((void**)&h, g_h);
    cudaGetSymbolAddress((void**)&h3, g_h3);
    cudaGetSymbolAddress((void**)&xhi, g_xhi);
    cudaGetSymbolAddress((void**)&xlo, g_xlo);
    cudaGetSymbolAddress((void**)&mhi, g_mhi);
    cudaGetSymbolAddress((void**)&mlo, g_mlo);
    cudaGetSymbolAddress((void**)&hhi, g_hhi);
    cudaGetSymbolAddress((void**)&hlo, g_hlo);
    cudaGetSymbolAddress((void**)&w, g_w);
    const size_t WSTRIDE = 256 * 128;
    __nv_bfloat16* wp[12];
    for (int i = 0; i < 12; i++) wp[i] = w + i * WSTRIDE;

    const int T = 256;
    const int SMEM_GEMM = 2 * 32768 + 128;    // double-buffered stages + align slack

    cudaFuncSetAttribute(gemm_mma<true>, cudaFuncAttributeMaxDynamicSharedMemorySize, SMEM_GEMM);
    cudaFuncSetAttribute(gemm_mma<false>, cudaFuncAttributeMaxDynamicSharedMemorySize, SMEM_GEMM);

    // degree (reused by all 3 layers)
    zero_kernel<<<cdiv(M, T), T>>>(deg, M);
    deg_kernel<<<cdiv(E, T), T>>>(dst, deg, E);

    // one-time splits: x and weights
    split_kernel<<<cdiv(M * IN_DIM, T), T>>>(x, xhi, xlo, M * IN_DIM);
    wsplit_kernel<<<cdiv(IN_DIM * HID, T), T>>>(Wl1, wp[0], wp[1], IN_DIM, HID);
    wsplit_kernel<<<cdiv(IN_DIM * HID, T), T>>>(Wr1, wp[2], wp[3], IN_DIM, HID);
    wsplit_kernel<<<cdiv(HID * HID, T), T>>>(Wl2, wp[4], wp[5], HID, HID);
    wsplit_kernel<<<cdiv(HID * HID, T), T>>>(Wr2, wp[6], wp[7], HID, HID);
    wsplit_kernel<<<cdiv(HID * 2 * HID, T), T>>>(Wl3, wp[8], wp[9], HID, 2 * HID);
    wsplit_kernel<<<cdiv(HID * 2 * HID, T), T>>>(Wr3, wp[10], wp[11], HID, 2 * HID);

    const int MT = cdiv(M, 128);   // 782 m-tiles

    // ---- layer 1: d = 64 -> 128 ----
    {
        const int d = IN_DIM, shift = 4;
        zero_kernel<<<cdiv(M * d, T), T>>>(agg, M * d);
        scatter_kernel<<<cdiv(E * (d / 4), T), T>>>((const float4*)x, src, dst, (float4*)agg, E, shift);
        mean_conv_kernel<<<cdiv(M * d, T), T>>>(agg, deg, mhi, mlo, M * d, 6);
        gemm_mma<true><<<dim3(MT, 1), 256, SMEM_GEMM>>>(
            mhi, mlo, xhi, xlo, wp[0], wp[1], wp[2], wp[3],
            bl1, h, hhi, hlo, M, HID, d);
    }
    // ---- layer 2: d = 128 -> 128 ----
    {
        const int d = HID, shift = 5;
        zero_kernel<<<cdiv(M * d, T), T>>>(agg, M * d);
        scatter_kernel<<<cdiv(E * (d / 4), T), T>>>((const float4*)h, src, dst, (float4*)agg, E, shift);
        mean_conv_kernel<<<cdiv(M * d, T), T>>>(agg, deg, mhi, mlo, M * d, 7);
        gemm_mma<true><<<dim3(MT, 1), 256, SMEM_GEMM>>>(
            mhi, mlo, hhi, hlo, wp[4], wp[5], wp[6], wp[7],
            bl2, h, hhi, hlo, M, HID, d);
    }
    // ---- layer 3: d = 128 -> 256 ----
    {
        const int d = HID, shift = 5;
        zero_kernel<<<cdiv(M * d, T), T>>>(agg, M * d);
        scatter_kernel<<<cdiv(E * (d / 4), T), T>>>((const float4*)h, src, dst, (float4*)agg, E, shift);
        mean_conv_kernel<<<cdiv(M * d, T), T>>>(agg, deg, mhi, mlo, M * d, 7);
        gemm_mma<false><<<dim3(MT, 2), 256, SMEM_GEMM>>>(
            mhi, mlo, hhi, hlo, wp[8], wp[9], wp[10], wp[11],
            bl3, h3, nullptr, nullptr, M, 2 * HID, d);
    }
    // ---- FC head ----
    fc_kernel<<<cdiv(M * 32, T), T>>>(h3, Wfc, bfc, out, M);
}

// round 6
// speedup vs baseline: 2.5619x; 1.9453x over previous
#include <cuda_runtime.h>
#include <cuda_bf16.h>
#include <cstdint>

// ---------------- problem constants ----------------
#define N_NODES 100000
#define N_EDGES 1600000
#define IN_DIM 64
#define HID 128
#define OUT_DIM 9

// ---------------- static scratch (no allocation allowed) ----------------
__device__ int g_cnt[N_NODES];
__device__ int g_start[N_NODES + 1];
__device__ int g_cursor[N_NODES];
__device__ int g_perm[N_EDGES];
__device__ int g_bsum[512];

__device__ __nv_bfloat16 g_xhi[(size_t)N_NODES * IN_DIM];
__device__ __nv_bfloat16 g_xlo[(size_t)N_NODES * IN_DIM];
__device__ __nv_bfloat16 g_mhi[(size_t)N_NODES * HID];         // mean hi
__device__ __nv_bfloat16 g_mlo[(size_t)N_NODES * HID];         // mean lo
__device__ float g_h[(size_t)N_NODES * HID];                   // h1 then h2 (fp32, gather source)
__device__ __nv_bfloat16 g_hhi[(size_t)N_NODES * HID];
__device__ __nv_bfloat16 g_hlo[(size_t)N_NODES * HID];
__device__ float g_h3[(size_t)N_NODES * 2 * HID];
// static weight buffers (bf16, transposed [N,K]); order: l1l_hi,l1l_lo,l1r_hi,l1r_lo, l2..., l3...
__device__ __nv_bfloat16 g_w[12][256 * 128];

// ---------------- PTX helpers (all plain sm_80+ — no 'a' features) ----------------
__device__ __forceinline__ uint32_t smem_u32(const void* p) {
    uint32_t a;
    asm("{ .reg .u64 t; cvta.to.shared.u64 t, %1; cvt.u32.u64 %0, t; }" : "=r"(a) : "l"(p));
    return a;
}

__device__ __forceinline__ void cp_async16(uint32_t dst, const void* src, int src_bytes) {
    asm volatile("cp.async.cg.shared.global [%0], [%1], 16, %2;"
                 :: "r"(dst), "l"(src), "r"(src_bytes));
}
#define CP_COMMIT() asm volatile("cp.async.commit_group;" ::: "memory")
#define CP_WAIT_1() asm volatile("cp.async.wait_group 1;" ::: "memory")

__device__ __forceinline__ void ldm_x4(uint32_t& r0, uint32_t& r1, uint32_t& r2, uint32_t& r3,
                                       uint32_t addr) {
    asm volatile("ldmatrix.sync.aligned.m8n8.x4.shared.b16 {%0,%1,%2,%3}, [%4];"
                 : "=r"(r0), "=r"(r1), "=r"(r2), "=r"(r3) : "r"(addr));
}

__device__ __forceinline__ void mma_16816(float* c, const uint32_t* a, const uint32_t* b) {
    asm volatile(
        "mma.sync.aligned.m16n8k16.row.col.f32.bf16.bf16.f32 "
        "{%0,%1,%2,%3}, {%4,%5,%6,%7}, {%8,%9}, {%0,%1,%2,%3};"
        : "+f"(c[0]), "+f"(c[1]), "+f"(c[2]), "+f"(c[3])
        : "r"(a[0]), "r"(a[1]), "r"(a[2]), "r"(a[3]), "r"(b[0]), "r"(b[1]));
}

// ---------------- CSR build kernels ----------------
__global__ void zero_int(int* __restrict__ p, int n) {
    int i = blockIdx.x * blockDim.x + threadIdx.x;
    if (i < n) p[i] = 0;
}

__global__ void hist_kernel(const int* __restrict__ dst, int* __restrict__ cnt, int E) {
    int e = blockIdx.x * blockDim.x + threadIdx.x;
    if (e < E) atomicAdd(&cnt[dst[e]], 1);
}

#define SCAN_B 256
__global__ void block_sum(const int* __restrict__ cnt, int* __restrict__ bsum, int n) {
    __shared__ int sh[SCAN_B];
    int i = blockIdx.x * SCAN_B + threadIdx.x;
    sh[threadIdx.x] = (i < n) ? cnt[i] : 0;
    __syncthreads();
    #pragma unroll
    for (int off = SCAN_B / 2; off > 0; off >>= 1) {
        if (threadIdx.x < off) sh[threadIdx.x] += sh[threadIdx.x + off];
        __syncthreads();
    }
    if (threadIdx.x == 0) bsum[blockIdx.x] = sh[0];
}

// single block of 512 threads: exclusive scan of nb block sums; also writes start[N]=E total
__global__ void scan_bsums(int* __restrict__ bsum, int nb, int* __restrict__ startN) {
    __shared__ int sh[512];
    int t = threadIdx.x;
    int orig = (t < nb) ? bsum[t] : 0;
    sh[t] = orig;
    __syncthreads();
    #pragma unroll
    for (int off = 1; off < 512; off <<= 1) {
        int v = (t >= off) ? sh[t - off] : 0;
        __syncthreads();
        sh[t] += v;
        __syncthreads();
    }
    if (t < nb) bsum[t] = sh[t] - orig;   // exclusive prefix
    if (t == 0) startN[0] = sh[511];      // total = E
}

__global__ void block_scan(const int* __restrict__ cnt, const int* __restrict__ boff,
                           int* __restrict__ start, int* __restrict__ cursor, int n) {
    __shared__ int sh[SCAN_B];
    int i = blockIdx.x * SCAN_B + threadIdx.x;
    int t = threadIdx.x;
    int v = (i < n) ? cnt[i] : 0;
    sh[t] = v;
    __syncthreads();
    #pragma unroll
    for (int off = 1; off < SCAN_B; off <<= 1) {
        int u = (t >= off) ? sh[t - off] : 0;
        __syncthreads();
        sh[t] += u;
        __syncthreads();
    }
    if (i < n) {
        int ex = boff[blockIdx.x] + sh[t] - v;
        start[i] = ex;
        cursor[i] = ex;
    }
}

__global__ void fill_perm(const int* __restrict__ src, const int* __restrict__ dst,
                          int* __restrict__ cursor, int* __restrict__ perm, int E) {
    int e = blockIdx.x * blockDim.x + threadIdx.x;
    if (e < E) {
        int pos = atomicAdd(&cursor[dst[e]], 1);
        perm[pos] = src[e];
    }
}

// ---------------- CSR gather-aggregate + mean + bf16 hi/lo split ----------------
// DV = feature dim / 4 (float4 units per row). DV=32: warp per node. DV=16: 2 nodes per warp.
template <int DV>
__global__ __launch_bounds__(256)
void agg_csr(const float4* __restrict__ x, const int* __restrict__ start,
             const int* __restrict__ perm,
             __nv_bfloat16* __restrict__ hi, __nv_bfloat16* __restrict__ lo, int n) {
    int gw = (blockIdx.x * blockDim.x + threadIdx.x) >> 5;
    int lane = threadIdx.x & 31;
    int node, c;
    if (DV == 32) { node = gw; c = lane; }
    else          { node = gw * 2 + (lane >> 4); c = lane & 15; }
    if (node >= n) return;
    int s = __ldg(&start[node]);
    int e = __ldg(&start[node + 1]);
    float4 acc = make_float4(0.f, 0.f, 0.f, 0.f);
    int j = s;
    for (; j + 4 <= e; j += 4) {
        int p0 = __ldg(&perm[j]);
        int p1 = __ldg(&perm[j + 1]);
        int p2 = __ldg(&perm[j + 2]);
        int p3 = __ldg(&perm[j + 3]);
        float4 v0 = __ldg(&x[(size_t)p0 * DV + c]);
        float4 v1 = __ldg(&x[(size_t)p1 * DV + c]);
        float4 v2 = __ldg(&x[(size_t)p2 * DV + c]);
        float4 v3 = __ldg(&x[(size_t)p3 * DV + c]);
        acc.x += v0.x + v1.x + v2.x + v3.x;
        acc.y += v0.y + v1.y + v2.y + v3.y;
        acc.z += v0.z + v1.z + v2.z + v3.z;
        acc.w += v0.w + v1.w + v2.w + v3.w;
    }
    for (; j < e; j++) {
        int p = __ldg(&perm[j]);
        float4 v = __ldg(&x[(size_t)p * DV + c]);
        acc.x += v.x; acc.y += v.y; acc.z += v.z; acc.w += v.w;
    }
    float r = 1.0f / fmaxf((float)(e - s), 1.0f);
    float m[4] = {acc.x * r, acc.y * r, acc.z * r, acc.w * r};
    __nv_bfloat16 hb[4], lb[4];
    #pragma unroll
    for (int q = 0; q < 4; q++) {
        hb[q] = __float2bfloat16(m[q]);
        lb[q] = __float2bfloat16(m[q] - __bfloat162float(hb[q]));
    }
    size_t off = (size_t)node * (DV * 4) + c * 4;
    *(uint2*)(hi + off) = *(uint2*)hb;
    *(uint2*)(lo + off) = *(uint2*)lb;
}

// ---------------- misc split kernels ----------------
__global__ void split_kernel(const float* __restrict__ x,
                             __nv_bfloat16* __restrict__ hi, __nv_bfloat16* __restrict__ lo, int n) {
    int i = blockIdx.x * blockDim.x + threadIdx.x;
    if (i >= n) return;
    float v = x[i];
    __nv_bfloat16 h = __float2bfloat16(v);
    hi[i] = h;
    lo[i] = __float2bfloat16(v - __bfloat162float(h));
}

__global__ void wsplit_kernel(const float* __restrict__ W,
                              __nv_bfloat16* __restrict__ hi, __nv_bfloat16* __restrict__ lo,
                              int K, int N) {
    int idx = blockIdx.x * blockDim.x + threadIdx.x;
    if (idx >= K * N) return;
    int k = idx / N, n = idx % N;
    float v = W[idx];
    __nv_bfloat16 h = __float2bfloat16(v);
    hi[(size_t)n * K + k] = h;
    lo[(size_t)n * K + k] = __float2bfloat16(v - __bfloat162float(h));
}

// ---------------- mma.sync dual-A split-bf16 GEMM (unchanged from R5, passing) ----------------
template <bool SPLIT_OUT>
__global__ __launch_bounds__(256, 2)
void gemm_mma(const __nv_bfloat16* __restrict__ A1hi, const __nv_bfloat16* __restrict__ A1lo,
              const __nv_bfloat16* __restrict__ A2hi, const __nv_bfloat16* __restrict__ A2lo,
              const __nv_bfloat16* __restrict__ B1hi, const __nv_bfloat16* __restrict__ B1lo,
              const __nv_bfloat16* __restrict__ B2hi, const __nv_bfloat16* __restrict__ B2lo,
              const float* __restrict__ bias, float* __restrict__ C,
              __nv_bfloat16* __restrict__ Chi, __nv_bfloat16* __restrict__ Clo,
              int M, int Ntot, int Kseg) {
    extern __shared__ char smem_raw[];
    char* smem = (char*)(((uintptr_t)smem_raw + 127) & ~(uintptr_t)127);
    const uint32_t sbase = smem_u32(smem);

    const int tid = threadIdx.x;
    const int wid = tid >> 5;
    const int lane = tid & 31;
    const int warp_m = wid & 3;
    const int warp_n = wid >> 2;
    const int bm = blockIdx.x * 128;
    const int bn = blockIdx.y * 128;

    const int STG = 32768;
    const int BOFF = 16384;

    const __nv_bfloat16* As[6] = {A1hi, A1hi, A1lo, A2hi, A2hi, A2lo};
    const __nv_bfloat16* Bs[6] = {B1hi, B1lo, B1hi, B2hi, B2lo, B2hi};
    const int cps = Kseg >> 6;
    const int nch = 6 * cps;

    float acc[2][8][4];
    #pragma unroll
    for (int mi = 0; mi < 2; mi++)
        #pragma unroll
        for (int ni = 0; ni < 8; ni++)
            #pragma unroll
            for (int q = 0; q < 4; q++) acc[mi][ni][q] = 0.0f;

    auto load_stage = [&](int stage, int c) {
        const int seg = c / cps;
        const int sub = c - seg * cps;
        const __nv_bfloat16* Ab = As[seg];
        const __nv_bfloat16* Bb = Bs[seg];
        const int kofs = sub << 6;
        #pragma unroll
        for (int p = 0; p < 4; p++) {
            int ci = tid + p * 256;
            int row = ci >> 3;
            int ch = ci & 7;
            uint32_t dstp = sbase + stage * STG + row * 128 + ((ch ^ (row & 7)) << 4);
            int grow = bm + row;
            int ok = (grow < M) ? 16 : 0;
            int gr = (grow < M) ? grow : (M - 1);
            cp_async16(dstp, Ab + (size_t)gr * Kseg + kofs + ch * 8, ok);
        }
        #pragma unroll
        for (int p = 0; p < 4; p++) {
            int ci = tid + p * 256;
            int row = ci >> 3;
            int ch = ci & 7;
            uint32_t dstp = sbase + stage * STG + BOFF + row * 128 + ((ch ^ (row & 7)) << 4);
            cp_async16(dstp, Bb + (size_t)(bn + row) * Kseg + kofs + ch * 8, 16);
        }
    };

    const int arow = warp_m * 32 + (lane & 15);
    const int asel = (lane >> 4);
    const int brow = warp_n * 64 + (lane & 7) + ((lane & 16) >> 1);
    const int bsel = (lane >> 3) & 1;

    load_stage(0, 0);
    CP_COMMIT();

    for (int c = 0; c < nch; c++) {
        const int s = c & 1;
        if (c + 1 < nch) load_stage(s ^ 1, c + 1);
        CP_COMMIT();
        CP_WAIT_1();
        __syncthreads();

        const uint32_t Abase = sbase + s * STG;
        const uint32_t Bbase = sbase + s * STG + BOFF;
        #pragma unroll
        for (int kc = 0; kc < 4; kc++) {
            uint32_t a[2][4];
            #pragma unroll
            for (int mi = 0; mi < 2; mi++) {
                int r = arow + mi * 16;
                uint32_t ad = Abase + r * 128 + (((kc * 2 + asel) ^ (r & 7)) << 4);
                ldm_x4(a[mi][0], a[mi][1], a[mi][2], a[mi][3], ad);
            }
            uint32_t b[8][2];
            #pragma unroll
            for (int nj = 0; nj < 4; nj++) {
                int r = brow + nj * 16;
                uint32_t bd = Bbase + r * 128 + (((kc * 2 + bsel) ^ (r & 7)) << 4);
                uint32_t t0, t1, t2, t3;
                ldm_x4(t0, t1, t2, t3, bd);
                b[nj * 2][0] = t0; b[nj * 2][1] = t1;
                b[nj * 2 + 1][0] = t2; b[nj * 2 + 1][1] = t3;
            }
            #pragma unroll
            for (int mi = 0; mi < 2; mi++)
                #pragma unroll
                for (int ni = 0; ni < 8; ni++)
                    mma_16816(acc[mi][ni], a[mi], b[ni]);
        }
        __syncthreads();
    }

    const int col0 = bn + warp_n * 64 + (lane & 3) * 2;
    #pragma unroll
    for (int mi = 0; mi < 2; mi++) {
        int row0 = bm + warp_m * 32 + mi * 16 + (lane >> 2);
        #pragma unroll
        for (int half = 0; half < 2; half++) {
            int row = row0 + half * 8;
            if (row >= M) continue;
            #pragma unroll
            for (int ni = 0; ni < 8; ni++) {
                int col = col0 + ni * 8;
                float v0 = acc[mi][ni][half * 2 + 0] + __ldg(&bias[col]);
                float v1 = acc[mi][ni][half * 2 + 1] + __ldg(&bias[col + 1]);
                v0 = fmaxf(v0, 0.0f);
                v1 = fmaxf(v1, 0.0f);
                *(float2*)(C + (size_t)row * Ntot + col) = make_float2(v0, v1);
                if (SPLIT_OUT) {
                    __nv_bfloat16 h0 = __float2bfloat16(v0);
                    __nv_bfloat16 h1 = __float2bfloat16(v1);
                    __nv_bfloat16 l0 = __float2bfloat16(v0 - __bfloat162float(h0));
                    __nv_bfloat16 l1 = __float2bfloat16(v1 - __bfloat162float(h1));
                    *(__nv_bfloat162*)(Chi + (size_t)row * Ntot + col) = __nv_bfloat162(h0, h1);
                    *(__nv_bfloat162*)(Clo + (size_t)row * Ntot + col) = __nv_bfloat162(l0, l1);
                }
            }
        }
    }
}

// ---------------- FC head: out[i,0..8] = h3[i,:]@Wfc + bfc (warp per node) ----
__global__ void fc_kernel(const float* __restrict__ h3, const float* __restrict__ W,
                          const float* __restrict__ b, float* __restrict__ out, int M) {
    int gwarp = (blockIdx.x * blockDim.x + threadIdx.x) >> 5;
    int lane = threadIdx.x & 31;
    if (gwarp >= M) return;
    const float* row = h3 + (size_t)gwarp * (2 * HID);
    float acc[OUT_DIM];
    #pragma unroll
    for (int j = 0; j < OUT_DIM; j++) acc[j] = 0.0f;
    for (int k = lane; k < 2 * HID; k += 32) {
        float a = row[k];
        #pragma unroll
        for (int j = 0; j < OUT_DIM; j++)
            acc[j] = fmaf(a, W[k * OUT_DIM + j], acc[j]);
    }
    #pragma unroll
    for (int j = 0; j < OUT_DIM; j++) {
        #pragma unroll
        for (int off = 16; off > 0; off >>= 1)
            acc[j] += __shfl_down_sync(0xffffffffu, acc[j], off);
    }
    if (lane == 0) {
        #pragma unroll
        for (int j = 0; j < OUT_DIM; j++)
            out[(size_t)gwarp * OUT_DIM + j] = acc[j] + b[j];
    }
}

// ---------------- host launch ----------------
static inline int cdiv(int a, int b) { return (a + b - 1) / b; }

extern "C" void kernel_launch(void* const* d_in, const int* in_sizes, int n_in,
                              void* d_out, int out_size) {
    const float* x   = (const float*)d_in[0];
    const int* eidx  = (const int*)d_in[1];
    const float* Wl1 = (const float*)d_in[2];
    const float* bl1 = (const float*)d_in[3];
    const float* Wr1 = (const float*)d_in[4];
    const float* Wl2 = (const float*)d_in[5];
    const float* bl2 = (const float*)d_in[6];
    const float* Wr2 = (const float*)d_in[7];
    const float* Wl3 = (const float*)d_in[8];
    const float* bl3 = (const float*)d_in[9];
    const float* Wr3 = (const float*)d_in[10];
    const float* Wfc = (const float*)d_in[11];
    const float* bfc = (const float*)d_in[12];
    float* out = (float*)d_out;

    const int M = in_sizes[0] / IN_DIM;       // 100000
    const int E = in_sizes[1] / 2;            // 1600000
    const int* src = eidx;
    const int* dst = eidx + E;

    float *h, *h3;
    int *cnt, *start, *cursor, *perm, *bsum;
    __nv_bfloat16 *xhi, *xlo, *mhi, *mlo, *hhi, *hlo, *w;
    cudaGetSymbolAddress((void**)&cnt, g_cnt);
    cudaGetSymbolAddress((void**)&start, g_start);
    cudaGetSymbolAddress((void**)&cursor, g_cursor);
    cudaGetSymbolAddress((void**)&perm, g_perm);
    cudaGetSymbolAddress((void**)&bsum, g_bsum);
    cudaGetSymbolAddress((void**)&h, g_h);
    cudaGetSymbolAddress((void**)&h3, g_h3);
    cudaGetSymbolAddress((void**)&xhi, g_xhi);
    cudaGetSymbolAddress((void**)&xlo, g_xlo);
    cudaGetSymbolAddress((void**)&mhi, g_mhi);
    cudaGetSymbolAddress((void**)&mlo, g_mlo);
    cudaGetSymbolAddress((void**)&hhi, g_hhi);
    cudaGetSymbolAddress((void**)&hlo, g_hlo);
    cudaGetSymbolAddress((void**)&w, g_w);
    const size_t WSTRIDE = 256 * 128;
    __nv_bfloat16* wp[12];
    for (int i = 0; i < 12; i++) wp[i] = w + i * WSTRIDE;

    const int T = 256;
    const int SMEM_GEMM = 2 * 32768 + 128;

    cudaFuncSetAttribute(gemm_mma<true>, cudaFuncAttributeMaxDynamicSharedMemorySize, SMEM_GEMM);
    cudaFuncSetAttribute(gemm_mma<false>, cudaFuncAttributeMaxDynamicSharedMemorySize, SMEM_GEMM);

    // ---- CSR build (once per launch; reused by all 3 layers) ----
    const int NB = cdiv(M, SCAN_B);           // 391
    zero_int<<<cdiv(M, T), T>>>(cnt, M);
    hist_kernel<<<cdiv(E, T), T>>>(dst, cnt, E);
    block_sum<<<NB, SCAN_B>>>(cnt, bsum, M);
    scan_bsums<<<1, 512>>>(bsum, NB, start + M);
    block_scan<<<NB, SCAN_B>>>(cnt, bsum, start, cursor, M);
    fill_perm<<<cdiv(E, T), T>>>(src, dst, cursor, perm, E);

    // ---- one-time splits: x and weights ----
    split_kernel<<<cdiv(M * IN_DIM, T), T>>>(x, xhi, xlo, M * IN_DIM);
    wsplit_kernel<<<cdiv(IN_DIM * HID, T), T>>>(Wl1, wp[0], wp[1], IN_DIM, HID);
    wsplit_kernel<<<cdiv(IN_DIM * HID, T), T>>>(Wr1, wp[2], wp[3], IN_DIM, HID);
    wsplit_kernel<<<cdiv(HID * HID, T), T>>>(Wl2, wp[4], wp[5], HID, HID);
    wsplit_kernel<<<cdiv(HID * HID, T), T>>>(Wr2, wp[6], wp[7], HID, HID);
    wsplit_kernel<<<cdiv(HID * 2 * HID, T), T>>>(Wl3, wp[8], wp[9], HID, 2 * HID);
    wsplit_kernel<<<cdiv(HID * 2 * HID, T), T>>>(Wr3, wp[10], wp[11], HID, 2 * HID);

    const int MT = cdiv(M, 128);   // 782 m-tiles
    const int W128 = cdiv(M * 32, T);          // warp-per-node grids
    const int W64  = cdiv((M / 2 + 1) * 32, T);

    // ---- layer 1: d = 64 -> 128 ----
    agg_csr<16><<<W64, T>>>((const float4*)x, start, perm, mhi, mlo, M);
    gemm_mma<true><<<dim3(MT, 1), 256, SMEM_GEMM>>>(
        mhi, mlo, xhi, xlo, wp[0], wp[1], wp[2], wp[3],
        bl1, h, hhi, hlo, M, HID, IN_DIM);

    // ---- layer 2: d = 128 -> 128 ----
    agg_csr<32><<<W128, T>>>((const float4*)h, start, perm, mhi, mlo, M);
    gemm_mma<true><<<dim3(MT, 1), 256, SMEM_GEMM>>>(
        mhi, mlo, hhi, hlo, wp[4], wp[5], wp[6], wp[7],
        bl2, h, hhi, hlo, M, HID, HID);

    // ---- layer 3: d = 128 -> 256 ----
    agg_csr<32><<<W128, T>>>((const float4*)h, start, perm, mhi, mlo, M);
    gemm_mma<false><<<dim3(MT, 2), 256, SMEM_GEMM>>>(
        mhi, mlo, hhi, hlo, wp[8], wp[9], wp[10], wp[11],
        bl3, h3, nullptr, nullptr, M, 2 * HID, HID);

    // ---- FC head ----
    fc_kernel<<<cdiv(M * 32, T), T>>>(h3, Wfc, bfc, out, M);
}